// round 14
// baseline (speedup 1.0000x reference)
#include <cuda_runtime.h>
#include <cuda_bf16.h>
#include <cstdint>

#define NN      8192
#define NODE    256
#define DEG     16
#define NFEAT   128
#define NHID    256
#define NCLASS  64

// ---------------- device scratch (no allocation allowed) --------------------
__device__ float g_X  [NN * NFEAT];       // adj @ x
__device__ float g_H  [NN * NHID];        // relu(gX @ W1)
__device__ float g_T  [NN * NCLASS];      // gH @ W2
__device__ float g_W1t[NHID * NFEAT];     // W1^T
__device__ float g_W2t[NCLASS * NHID];    // W2^T

// pack two f32 -> bf16x2 (first arg = upper half)
__device__ __forceinline__ uint32_t bf2(float hi, float lo) {
    uint32_t r; asm("cvt.rn.bf16x2.f32 %0, %1, %2;" : "=r"(r) : "f"(hi), "f"(lo));
    return r;
}
__device__ __forceinline__ void mma_bf16(float c[4], const uint32_t a[4], const uint32_t b[2]) {
    asm volatile(
        "mma.sync.aligned.m16n8k16.row.col.f32.bf16.bf16.f32 "
        "{%0,%1,%2,%3}, {%4,%5,%6,%7}, {%8,%9}, {%0,%1,%2,%3};"
        : "+f"(c[0]), "+f"(c[1]), "+f"(c[2]), "+f"(c[3])
        : "r"(a[0]), "r"(a[1]), "r"(a[2]), "r"(a[3]), "r"(b[0]), "r"(b[1]));
}

// Dynamic smem sizes for agg1
#define A1_SMX_FLT   (NODE * 32)
#define A1_EDGE_INT  (NODE * DEG)
#define A1_SMEM_B    ((A1_SMX_FLT + A1_EDGE_INT + NODE + NODE) * 4)

// ---------------------------------------------------------------------------
// K1: blocks 0..127 : agg1 — smem-staged adj @ x. CTA = (block, 32-col slice).
//     blocks 128..175: W transposes. (R12-proven, keep-mask plumbing removed.)
// ---------------------------------------------------------------------------
__global__ __launch_bounds__(256)
void agg1_kernel(const float* __restrict__ x, const int* __restrict__ edge,
                 const float* __restrict__ W1, const float* __restrict__ W2,
                 float* __restrict__ gX, float* __restrict__ W1t,
                 float* __restrict__ W2t)
{
    extern __shared__ float dyn[];
    const int bid = blockIdx.x;
    const int tid = threadIdx.x;

    if (bid < 128) {
        float*    smx   = dyn;                                           // [256][32]
        int*      sedge = reinterpret_cast<int*>(dyn + A1_SMX_FLT);      // [256][16]
        unsigned* smask = reinterpret_cast<unsigned*>(sedge + A1_EDGE_INT);

        const int blk  = bid >> 2;
        const int g    = bid & 3;
        const int base = blk * NODE;

#pragma unroll
        for (int i = tid; i < NODE * 8; i += 256) {
            int r = i >> 3, qd = i & 7;
            *reinterpret_cast<float4*>(&smx[r * 32 + qd * 4]) =
                *reinterpret_cast<const float4*>(
                    x + (size_t)(base + r) * NFEAT + g * 32 + qd * 4);
        }
        {
            const int4* ep = reinterpret_cast<const int4*>(edge + (size_t)(base + tid) * DEG);
            int4 v0 = ep[0], v1 = ep[1], v2 = ep[2], v3 = ep[3];
            int e[16] = {v0.x, v0.y, v0.z, v0.w, v1.x, v1.y, v1.z, v1.w,
                         v2.x, v2.y, v2.z, v2.w, v3.x, v3.y, v3.z, v3.w};
            unsigned mask = 0;
#pragma unroll
            for (int i = 0; i < 16; ++i) {
                bool keep = e[i] >= 0;
#pragma unroll
                for (int p = 0; p < i; ++p) keep = keep && (e[i] != e[p]);
                if (keep) mask |= 1u << i;
                sedge[tid * DEG + i] = (e[i] >= 0) ? e[i] : 0;
            }
            smask[tid] = mask;
        }
        __syncthreads();

#pragma unroll
        for (int p = 0; p < 8; ++p) {
            const int nl = p * 32 + (tid >> 3);
            const int qd = tid & 7;
            const unsigned mask = smask[nl];
            float4 a = make_float4(0.f, 0.f, 0.f, 0.f);
#pragma unroll
            for (int t = 0; t < DEG; ++t) {
                int   j  = sedge[nl * DEG + t];
                float fm = (float)((mask >> t) & 1u);
                float4 v = *reinterpret_cast<const float4*>(&smx[j * 32 + qd * 4]);
                a.x = fmaf(v.x, fm, a.x);
                a.y = fmaf(v.y, fm, a.y);
                a.z = fmaf(v.z, fm, a.z);
                a.w = fmaf(v.w, fm, a.w);
            }
            *reinterpret_cast<float4*>(
                gX + (size_t)(base + nl) * NFEAT + g * 32 + qd * 4) = a;
        }
    } else {
        float* t = dyn;                         // [32][33]
        const float* src; float* dst; int R, C, tr, tc;
        if (bid < 160) { int b = bid - 128; src = W1; dst = W1t; R = NFEAT; C = NHID;  tr = b >> 3; tc = b & 7; }
        else           { int b = bid - 160; src = W2; dst = W2t; R = NHID;  C = NCLASS; tr = b >> 1; tc = b & 1; }
        const int r  = tid >> 3;
        const int fq = tid & 7;
        float4 v = *reinterpret_cast<const float4*>(src + (size_t)(tr * 32 + r) * C + tc * 32 + fq * 4);
        t[r * 33 + fq * 4 + 0] = v.x; t[r * 33 + fq * 4 + 1] = v.y;
        t[r * 33 + fq * 4 + 2] = v.z; t[r * 33 + fq * 4 + 3] = v.w;
        __syncthreads();
        float4 o;
        o.x = t[(fq * 4 + 0) * 33 + r]; o.y = t[(fq * 4 + 1) * 33 + r];
        o.z = t[(fq * 4 + 2) * 33 + r]; o.w = t[(fq * 4 + 3) * 33 + r];
        *reinterpret_cast<float4*>(dst + (size_t)(tc * 32 + r) * R + tr * 32 + fq * 4) = o;
    }
}

// ---------------------------------------------------------------------------
// bf16 mma.sync GEMM (m16n8k16), 3xBF16 compensation, double-buffered.
// (exact R12-proven kernel: on-the-fly split, fp32 in/out)
// ---------------------------------------------------------------------------
template<int BM, int BN, int KTOT, int WM, int WN, bool RELU>
__global__ __launch_bounds__(256)
void gemm_bf16(const float* __restrict__ A, const float* __restrict__ Bt,
               float* __restrict__ C, int ldc)
{
    constexpr int LW     = 20;
    constexpr int NWN    = BN / WN;
    constexpr int MSUB   = WM / 16;
    constexpr int NSUB   = WN / 8;
    constexpr int NCHUNK = KTOT / 32;
    constexpr int A_W    = BM * LW;
    constexpr int B_W    = BN * LW;
    constexpr int STAGE_W = 2 * A_W + 2 * B_W;
    constexpr int APT    = BM * 8 / 256;
    constexpr int BPT    = BN * 8 / 256;

    extern __shared__ uint32_t smw[];

    const int tid   = threadIdx.x;
    const int wid   = tid >> 5;
    const int lane  = tid & 31;
    const int brow  = blockIdx.x * BM;
    const int bcol  = blockIdx.y * BN;
    const int warpM = (wid / NWN) * WM;
    const int warpN = (wid % NWN) * WN;
    const int grp   = lane >> 2;
    const int qk    = lane & 3;

    float acc[MSUB][NSUB][4] = {};
    float4 pa[APT], pb[BPT];

#pragma unroll
    for (int j = 0; j < APT; ++j) {
        int i = tid + j * 256;
        pa[j] = *reinterpret_cast<const float4*>(
            A + (size_t)(brow + (i >> 3)) * KTOT + ((i & 7) << 2));
    }
#pragma unroll
    for (int j = 0; j < BPT; ++j) {
        int i = tid + j * 256;
        pb[j] = *reinterpret_cast<const float4*>(
            Bt + (size_t)(bcol + (i >> 3)) * KTOT + ((i & 7) << 2));
    }

    for (int c = 0; c < NCHUNK; ++c) {
        uint32_t* Ah = smw + (c & 1) * STAGE_W;
        uint32_t* Al = Ah + A_W;
        uint32_t* Bh = Al + A_W;
        uint32_t* Bl = Bh + B_W;

#pragma unroll
        for (int j = 0; j < APT; ++j) {
            int i = tid + j * 256;
            int r = i >> 3, f = i & 7;
            float4 v = pa[j];
            uint32_t h0 = bf2(v.y, v.x), h1 = bf2(v.w, v.z);
            float hx = __uint_as_float(h0 << 16), hy = __uint_as_float(h0 & 0xffff0000u);
            float hz = __uint_as_float(h1 << 16), hw = __uint_as_float(h1 & 0xffff0000u);
            uint32_t l0 = bf2(v.y - hy, v.x - hx), l1 = bf2(v.w - hw, v.z - hz);
            *reinterpret_cast<uint2*>(&Ah[r * LW + f * 2]) = make_uint2(h0, h1);
            *reinterpret_cast<uint2*>(&Al[r * LW + f * 2]) = make_uint2(l0, l1);
        }
#pragma unroll
        for (int j = 0; j < BPT; ++j) {
            int i = tid + j * 256;
            int r = i >> 3, f = i & 7;
            float4 v = pb[j];
            uint32_t h0 = bf2(v.y, v.x), h1 = bf2(v.w, v.z);
            float hx = __uint_as_float(h0 << 16), hy = __uint_as_float(h0 & 0xffff0000u);
            float hz = __uint_as_float(h1 << 16), hw = __uint_as_float(h1 & 0xffff0000u);
            uint32_t l0 = bf2(v.y - hy, v.x - hx), l1 = bf2(v.w - hw, v.z - hz);
            *reinterpret_cast<uint2*>(&Bh[r * LW + f * 2]) = make_uint2(h0, h1);
            *reinterpret_cast<uint2*>(&Bl[r * LW + f * 2]) = make_uint2(l0, l1);
        }
        if (c + 1 < NCHUNK) {
#pragma unroll
            for (int j = 0; j < APT; ++j) {
                int i = tid + j * 256;
                pa[j] = *reinterpret_cast<const float4*>(
                    A + (size_t)(brow + (i >> 3)) * KTOT + (c + 1) * 32 + ((i & 7) << 2));
            }
#pragma unroll
            for (int j = 0; j < BPT; ++j) {
                int i = tid + j * 256;
                pb[j] = *reinterpret_cast<const float4*>(
                    Bt + (size_t)(bcol + (i >> 3)) * KTOT + (c + 1) * 32 + ((i & 7) << 2));
            }
        }
        __syncthreads();

#pragma unroll
        for (int ks = 0; ks < 2; ++ks) {
            const int kw = ks * 8;
            uint32_t aH[MSUB][4], aL[MSUB][4];
#pragma unroll
            for (int ms = 0; ms < MSUB; ++ms) {
                int r0 = (warpM + ms * 16 + grp) * LW + kw + qk;
                int r1 = r0 + 8 * LW;
                aH[ms][0] = Ah[r0];     aH[ms][1] = Ah[r1];
                aH[ms][2] = Ah[r0 + 4]; aH[ms][3] = Ah[r1 + 4];
                aL[ms][0] = Al[r0];     aL[ms][1] = Al[r1];
                aL[ms][2] = Al[r0 + 4]; aL[ms][3] = Al[r1 + 4];
            }
            uint32_t bH[NSUB][2], bL[NSUB][2];
#pragma unroll
            for (int ns = 0; ns < NSUB; ++ns) {
                int b0 = (warpN + ns * 8 + grp) * LW + kw + qk;
                bH[ns][0] = Bh[b0]; bH[ns][1] = Bh[b0 + 4];
                bL[ns][0] = Bl[b0]; bL[ns][1] = Bl[b0 + 4];
            }
#pragma unroll
            for (int ms = 0; ms < MSUB; ++ms)
#pragma unroll
                for (int ns = 0; ns < NSUB; ++ns) {
                    mma_bf16(acc[ms][ns], aH[ms], bH[ns]);
                    mma_bf16(acc[ms][ns], aH[ms], bL[ns]);
                    mma_bf16(acc[ms][ns], aL[ms], bH[ns]);
                }
        }
        __syncthreads();
    }

#pragma unroll
    for (int ms = 0; ms < MSUB; ++ms)
#pragma unroll
        for (int ns = 0; ns < NSUB; ++ns) {
            int row = brow + warpM + ms * 16 + grp;
            int col = bcol + warpN + ns * 8 + 2 * qk;
            float2 v0 = make_float2(acc[ms][ns][0], acc[ms][ns][1]);
            float2 v1 = make_float2(acc[ms][ns][2], acc[ms][ns][3]);
            if (RELU) {
                v0.x = fmaxf(v0.x, 0.f); v0.y = fmaxf(v0.y, 0.f);
                v1.x = fmaxf(v1.x, 0.f); v1.y = fmaxf(v1.y, 0.f);
            }
            *reinterpret_cast<float2*>(C + (size_t)row * ldc + col)       = v0;
            *reinterpret_cast<float2*>(C + (size_t)(row + 8) * ldc + col) = v1;
        }
}

// ---------------------------------------------------------------------------
// K4: agg2 as bitmap-MMA + fused log_softmax.
// CTA = half node-block (128 rows), grid 64. T block staged+transposed in
// smem to bf16 hi/lo B operands; A synthesized exactly from edge bitmaps.
// ---------------------------------------------------------------------------
#define A2_RAW_W  (NODE * 65)        // raw T block, stride 65
#define A2_B_W    (64 * 132)         // Bh / Bl, stride 132 (conflict-free)
#define A2_SMEM_B ((A2_RAW_W + 2 * A2_B_W + 128 * 8) * 4)

__global__ __launch_bounds__(256)
void agg2_mma(const float* __restrict__ T, const int* __restrict__ edge,
              float* __restrict__ out)
{
    extern __shared__ uint32_t smw2[];
    float*    raw = reinterpret_cast<float*>(smw2);
    uint32_t* Bh  = smw2 + A2_RAW_W;
    uint32_t* Bl  = Bh + A2_B_W;
    uint32_t* bm  = Bl + A2_B_W;     // [128][8] bitmaps

    const int tid  = threadIdx.x;
    const int wid  = tid >> 5;
    const int lane = tid & 31;
    const int grp  = lane >> 2;
    const int qk   = lane & 3;
    const int blk  = blockIdx.x >> 1;
    const int half = blockIdx.x & 1;
    const int base  = blk * NODE;
    const int rbase = half * 128;     // CTA's local row offset within block

    // phase 1: stage T block (scalar STS to keep stride-65 alignment)
    for (int i = tid; i < NODE * 16; i += 256) {
        int r = i >> 4, c4 = (i & 15) << 2;
        float4 v = *reinterpret_cast<const float4*>(
            T + (size_t)(base + r) * NCLASS + c4);
        float* p = &raw[r * 65 + c4];
        p[0] = v.x; p[1] = v.y; p[2] = v.z; p[3] = v.w;
    }
    // phase 1b: bitmaps for this CTA's 128 rows (dedup + -1 skip free)
    if (tid < 128) {
        unsigned b[8] = {0, 0, 0, 0, 0, 0, 0, 0};
        const int4* ep = reinterpret_cast<const int4*>(
            edge + (size_t)(base + rbase + tid) * DEG);
#pragma unroll
        for (int w = 0; w < 4; ++w) {
            int4 e4 = ep[w];
            if (e4.x >= 0) b[e4.x >> 5] |= 1u << (e4.x & 31);
            if (e4.y >= 0) b[e4.y >> 5] |= 1u << (e4.y & 31);
            if (e4.z >= 0) b[e4.z >> 5] |= 1u << (e4.z & 31);
            if (e4.w >= 0) b[e4.w >> 5] |= 1u << (e4.w & 31);
        }
#pragma unroll
        for (int w = 0; w < 8; ++w) bm[tid * 8 + w] = b[w];
    }
    __syncthreads();

    // phase 2: transpose-convert raw -> Bh/Bl  (word kw packs nodes 2kw,2kw+1)
    for (int idx = tid; idx < 64 * 128; idx += 256) {
        int n = idx >> 7, kw = idx & 127;
        float v0 = raw[(2 * kw) * 65 + n];
        float v1 = raw[(2 * kw + 1) * 65 + n];
        uint32_t h = bf2(v1, v0);
        float h0 = __uint_as_float(h << 16), h1 = __uint_as_float(h & 0xffff0000u);
        Bh[n * 132 + kw] = h;
        Bl[n * 132 + kw] = bf2(v1 - h1, v0 - h0);
    }
    __syncthreads();

    // phase 3: MMA — warp wid covers local rows wid*16 + {grp, grp+8}
    float acc[8][4] = {};
    const int lr = wid * 16 + grp;    // local row (0..127)
#pragma unroll
    for (int kc = 0; kc < 16; ++kc) {
        const int wi = kc >> 1, sh = (kc & 1) << 4;
        unsigned s0 = bm[lr * 8 + wi] >> sh;
        unsigned s1 = bm[(lr + 8) * 8 + wi] >> sh;
        uint32_t a[4];
        a[0] = ((s0 >> (2 * qk)) & 1u) * 0x3F80u | ((s0 >> (2 * qk + 1)) & 1u) * 0x3F800000u;
        a[1] = ((s1 >> (2 * qk)) & 1u) * 0x3F80u | ((s1 >> (2 * qk + 1)) & 1u) * 0x3F800000u;
        a[2] = ((s0 >> (8 + 2 * qk)) & 1u) * 0x3F80u | ((s0 >> (9 + 2 * qk)) & 1u) * 0x3F800000u;
        a[3] = ((s1 >> (8 + 2 * qk)) & 1u) * 0x3F80u | ((s1 >> (9 + 2 * qk)) & 1u) * 0x3F800000u;
#pragma unroll
        for (int ns = 0; ns < 8; ++ns) {
            int n = ns * 8 + grp;
            uint32_t bh[2] = {Bh[n * 132 + kc * 8 + qk], Bh[n * 132 + kc * 8 + 4 + qk]};
            uint32_t bl[2] = {Bl[n * 132 + kc * 8 + qk], Bl[n * 132 + kc * 8 + 4 + qk]};
            mma_bf16(acc[ns], a, bh);
            mma_bf16(acc[ns], a, bl);
        }
    }

    // phase 4: fused log_softmax + store (rows base+rbase+lr, +8)
    float m0 = -1e30f, m1 = -1e30f;
#pragma unroll
    for (int ns = 0; ns < 8; ++ns) {
        m0 = fmaxf(m0, fmaxf(acc[ns][0], acc[ns][1]));
        m1 = fmaxf(m1, fmaxf(acc[ns][2], acc[ns][3]));
    }
    m0 = fmaxf(m0, __shfl_xor_sync(0xffffffffu, m0, 1));
    m0 = fmaxf(m0, __shfl_xor_sync(0xffffffffu, m0, 2));
    m1 = fmaxf(m1, __shfl_xor_sync(0xffffffffu, m1, 1));
    m1 = fmaxf(m1, __shfl_xor_sync(0xffffffffu, m1, 2));
    float s0 = 0.f, s1 = 0.f;
#pragma unroll
    for (int ns = 0; ns < 8; ++ns) {
        s0 += expf(acc[ns][0] - m0) + expf(acc[ns][1] - m0);
        s1 += expf(acc[ns][2] - m1) + expf(acc[ns][3] - m1);
    }
    s0 += __shfl_xor_sync(0xffffffffu, s0, 1);
    s0 += __shfl_xor_sync(0xffffffffu, s0, 2);
    s1 += __shfl_xor_sync(0xffffffffu, s1, 1);
    s1 += __shfl_xor_sync(0xffffffffu, s1, 2);
    float lse0 = logf(s0) + m0;
    float lse1 = logf(s1) + m1;

    const int gr0 = base + rbase + lr;
#pragma unroll
    for (int ns = 0; ns < 8; ++ns) {
        int col = ns * 8 + 2 * qk;
        *reinterpret_cast<float2*>(out + (size_t)gr0 * NCLASS + col) =
            make_float2(acc[ns][0] - lse0, acc[ns][1] - lse0);
        *reinterpret_cast<float2*>(out + (size_t)(gr0 + 8) * NCLASS + col) =
            make_float2(acc[ns][2] - lse1, acc[ns][3] - lse1);
    }
}

// ---------------------------------------------------------------------------
extern "C" void kernel_launch(void* const* d_in, const int* in_sizes, int n_in,
                              void* d_out, int out_size)
{
    const float* x    = (const float*)d_in[0];
    const int*   edge = (const int*)  d_in[1];
    const float* W1   = (const float*)d_in[2];
    const float* W2   = (const float*)d_in[3];
    float* out = (float*)d_out;

    float *gX, *gH, *gT, *gW1t, *gW2t;
    cudaGetSymbolAddress((void**)&gX,   g_X);
    cudaGetSymbolAddress((void**)&gH,   g_H);
    cudaGetSymbolAddress((void**)&gT,   g_T);
    cudaGetSymbolAddress((void**)&gW1t, g_W1t);
    cudaGetSymbolAddress((void**)&gW2t, g_W2t);

    constexpr int SMEM1 = 2 * (2 * 128 + 2 * 128) * 20 * 4;   // 81920
    constexpr int SMEM2 = 2 * (2 * 64 + 2 * 64) * 20 * 4;     // 40960
    cudaFuncSetAttribute(agg1_kernel,
                         cudaFuncAttributeMaxDynamicSharedMemorySize, A1_SMEM_B);
    cudaFuncSetAttribute(gemm_bf16<128, 128, 128, 64, 32, true>,
                         cudaFuncAttributeMaxDynamicSharedMemorySize, SMEM1);
    cudaFuncSetAttribute(gemm_bf16<64, 64, 256, 32, 16, false>,
                         cudaFuncAttributeMaxDynamicSharedMemorySize, SMEM2);
    cudaFuncSetAttribute(agg2_mma,
                         cudaFuncAttributeMaxDynamicSharedMemorySize, A2_SMEM_B);

    // K1: gX = adj @ x (smem-staged) + W transposes
    agg1_kernel<<<176, 256, A1_SMEM_B>>>(x, edge, W1, W2, gX, gW1t, gW2t);
    // K2: gH = relu(gX @ W1)
    gemm_bf16<128, 128, 128, 64, 32, true>
        <<<dim3(64, 2), 256, SMEM1>>>(gX, gW1t, gH, NHID);
    // K3: gT = gH @ W2
    gemm_bf16<64, 64, 256, 32, 16, false>
        <<<dim3(128, 1), 256, SMEM2>>>(gH, gW2t, gT, NCLASS);
    // K4: out = log_softmax(adj @ gT)  via bitmap-MMA
    agg2_mma<<<64, 256, A2_SMEM_B>>>(gT, edge, out);
}

// round 15
// speedup vs baseline: 1.0060x; 1.0060x over previous
#include <cuda_runtime.h>
#include <cuda_bf16.h>
#include <cstdint>

#define NN      8192
#define NODE    256
#define DEG     16
#define NFEAT   128
#define NHID    256
#define NCLASS  64

// ---------------- device scratch (no allocation allowed) --------------------
__device__ float    g_X  [NN * NFEAT];    // adj @ x
__device__ float    g_H  [NN * NHID];     // relu(gX @ W1)
__device__ float    g_T  [NN * NCLASS];   // gH @ W2
__device__ unsigned g_keep[NN];           // dedup bitmask per node
__device__ float    g_W1t[NHID * NFEAT];  // W1^T
__device__ float    g_W2t[NCLASS * NHID]; // W2^T

// pack two f32 -> bf16x2 (hi arg = upper half)
__device__ __forceinline__ uint32_t bf2(float hi, float lo) {
    uint32_t r; asm("cvt.rn.bf16x2.f32 %0, %1, %2;" : "=r"(r) : "f"(hi), "f"(lo));
    return r;
}
__device__ __forceinline__ void mma_bf16(float c[4], const uint32_t a[4], const uint32_t b[2]) {
    asm volatile(
        "mma.sync.aligned.m16n8k16.row.col.f32.bf16.bf16.f32 "
        "{%0,%1,%2,%3}, {%4,%5,%6,%7}, {%8,%9}, {%0,%1,%2,%3};"
        : "+f"(c[0]), "+f"(c[1]), "+f"(c[2]), "+f"(c[3])
        : "r"(a[0]), "r"(a[1]), "r"(a[2]), "r"(a[3]), "r"(b[0]), "r"(b[1]));
}

// Dynamic smem sizes for agg1
#define A1_SMX_FLT   (NODE * 32)
#define A1_EDGE_INT  (NODE * DEG)
#define A1_SMEM_B    ((A1_SMX_FLT + A1_EDGE_INT + NODE + NODE) * 4)

// ---------------------------------------------------------------------------
// K1: blocks 0..127 : agg1 — smem-staged adj @ x. CTA = (block, 32-col slice).
//     Also writes dedup masks (g==0 CTAs). blocks 128..175: W transposes.
// ---------------------------------------------------------------------------
__global__ __launch_bounds__(256)
void agg1_kernel(const float* __restrict__ x, const int* __restrict__ edge,
                 const float* __restrict__ W1, const float* __restrict__ W2,
                 float* __restrict__ gX, unsigned* __restrict__ keep_out,
                 float* __restrict__ W1t, float* __restrict__ W2t)
{
    extern __shared__ float dyn[];
    const int bid = blockIdx.x;
    const int tid = threadIdx.x;

    if (bid < 128) {
        float*    smx   = dyn;                                           // [256][32]
        int*      sedge = reinterpret_cast<int*>(dyn + A1_SMX_FLT);      // [256][16]
        unsigned* smask = reinterpret_cast<unsigned*>(sedge + A1_EDGE_INT);

        const int blk  = bid >> 2;
        const int g    = bid & 3;
        const int base = blk * NODE;

#pragma unroll
        for (int i = tid; i < NODE * 8; i += 256) {
            int r = i >> 3, qd = i & 7;
            *reinterpret_cast<float4*>(&smx[r * 32 + qd * 4]) =
                *reinterpret_cast<const float4*>(
                    x + (size_t)(base + r) * NFEAT + g * 32 + qd * 4);
        }
        {
            const int4* ep = reinterpret_cast<const int4*>(edge + (size_t)(base + tid) * DEG);
            int4 v0 = ep[0], v1 = ep[1], v2 = ep[2], v3 = ep[3];
            int e[16] = {v0.x, v0.y, v0.z, v0.w, v1.x, v1.y, v1.z, v1.w,
                         v2.x, v2.y, v2.z, v2.w, v3.x, v3.y, v3.z, v3.w};
            unsigned mask = 0;
#pragma unroll
            for (int i = 0; i < 16; ++i) {
                bool keep = e[i] >= 0;
#pragma unroll
                for (int p = 0; p < i; ++p) keep = keep && (e[i] != e[p]);
                if (keep) mask |= 1u << i;
                sedge[tid * DEG + i] = (e[i] >= 0) ? e[i] : 0;
            }
            smask[tid] = mask;
            if (g == 0) keep_out[base + tid] = mask;
        }
        __syncthreads();

#pragma unroll
        for (int p = 0; p < 8; ++p) {
            const int nl = p * 32 + (tid >> 3);
            const int qd = tid & 7;
            const unsigned mask = smask[nl];
            float4 a = make_float4(0.f, 0.f, 0.f, 0.f);
#pragma unroll
            for (int t = 0; t < DEG; ++t) {
                int   j  = sedge[nl * DEG + t];
                float fm = (float)((mask >> t) & 1u);
                float4 v = *reinterpret_cast<const float4*>(&smx[j * 32 + qd * 4]);
                a.x = fmaf(v.x, fm, a.x);
                a.y = fmaf(v.y, fm, a.y);
                a.z = fmaf(v.z, fm, a.z);
                a.w = fmaf(v.w, fm, a.w);
            }
            *reinterpret_cast<float4*>(
                gX + (size_t)(base + nl) * NFEAT + g * 32 + qd * 4) = a;
        }
    } else {
        float* t = dyn;                         // [32][33]
        const float* src; float* dst; int R, C, tr, tc;
        if (bid < 160) { int b = bid - 128; src = W1; dst = W1t; R = NFEAT; C = NHID;  tr = b >> 3; tc = b & 7; }
        else           { int b = bid - 160; src = W2; dst = W2t; R = NHID;  C = NCLASS; tr = b >> 1; tc = b & 1; }
        const int r  = tid >> 3;
        const int fq = tid & 7;
        float4 v = *reinterpret_cast<const float4*>(src + (size_t)(tr * 32 + r) * C + tc * 32 + fq * 4);
        t[r * 33 + fq * 4 + 0] = v.x; t[r * 33 + fq * 4 + 1] = v.y;
        t[r * 33 + fq * 4 + 2] = v.z; t[r * 33 + fq * 4 + 3] = v.w;
        __syncthreads();
        float4 o;
        o.x = t[(fq * 4 + 0) * 33 + r]; o.y = t[(fq * 4 + 1) * 33 + r];
        o.z = t[(fq * 4 + 2) * 33 + r]; o.w = t[(fq * 4 + 3) * 33 + r];
        *reinterpret_cast<float4*>(dst + (size_t)(tc * 32 + r) * R + tr * 32 + fq * 4) = o;
    }
#if __CUDA_ARCH__ >= 900
    cudaTriggerProgrammaticLaunchCompletion();
#endif
}

// ---------------------------------------------------------------------------
// bf16 mma.sync GEMM (m16n8k16), 3xBF16 compensation, double-buffered.
// PDL: grid-dependency sync before first dependent load.
// ---------------------------------------------------------------------------
template<int BM, int BN, int KTOT, int WM, int WN, bool RELU>
__global__ __launch_bounds__(256)
void gemm_bf16(const float* __restrict__ A, const float* __restrict__ Bt,
               float* __restrict__ C, int ldc)
{
    constexpr int LW     = 20;                // words per 32-k row (16 + 4 pad)
    constexpr int NWN    = BN / WN;
    constexpr int MSUB   = WM / 16;
    constexpr int NSUB   = WN / 8;
    constexpr int NCHUNK = KTOT / 32;
    constexpr int A_W    = BM * LW;
    constexpr int B_W    = BN * LW;
    constexpr int STAGE_W = 2 * A_W + 2 * B_W;
    constexpr int APT    = BM * 8 / 256;
    constexpr int BPT    = BN * 8 / 256;

    extern __shared__ uint32_t smw[];

    const int tid   = threadIdx.x;
    const int wid   = tid >> 5;
    const int lane  = tid & 31;
    const int brow  = blockIdx.x * BM;
    const int bcol  = blockIdx.y * BN;
    const int warpM = (wid / NWN) * WM;
    const int warpN = (wid % NWN) * WN;
    const int grp   = lane >> 2;
    const int qk    = lane & 3;

    float acc[MSUB][NSUB][4] = {};
    float4 pa[APT], pb[BPT];

#if __CUDA_ARCH__ >= 900
    cudaGridDependencySynchronize();          // inputs come from prior kernel
#endif

#pragma unroll
    for (int j = 0; j < APT; ++j) {
        int i = tid + j * 256;
        pa[j] = *reinterpret_cast<const float4*>(
            A + (size_t)(brow + (i >> 3)) * KTOT + ((i & 7) << 2));
    }
#pragma unroll
    for (int j = 0; j < BPT; ++j) {
        int i = tid + j * 256;
        pb[j] = *reinterpret_cast<const float4*>(
            Bt + (size_t)(bcol + (i >> 3)) * KTOT + ((i & 7) << 2));
    }

    for (int c = 0; c < NCHUNK; ++c) {
        uint32_t* Ah = smw + (c & 1) * STAGE_W;
        uint32_t* Al = Ah + A_W;
        uint32_t* Bh = Al + A_W;
        uint32_t* Bl = Bh + B_W;

#pragma unroll
        for (int j = 0; j < APT; ++j) {
            int i = tid + j * 256;
            int r = i >> 3, f = i & 7;
            float4 v = pa[j];
            uint32_t h0 = bf2(v.y, v.x), h1 = bf2(v.w, v.z);
            float hx = __uint_as_float(h0 << 16), hy = __uint_as_float(h0 & 0xffff0000u);
            float hz = __uint_as_float(h1 << 16), hw = __uint_as_float(h1 & 0xffff0000u);
            uint32_t l0 = bf2(v.y - hy, v.x - hx), l1 = bf2(v.w - hw, v.z - hz);
            *reinterpret_cast<uint2*>(&Ah[r * LW + f * 2]) = make_uint2(h0, h1);
            *reinterpret_cast<uint2*>(&Al[r * LW + f * 2]) = make_uint2(l0, l1);
        }
#pragma unroll
        for (int j = 0; j < BPT; ++j) {
            int i = tid + j * 256;
            int r = i >> 3, f = i & 7;
            float4 v = pb[j];
            uint32_t h0 = bf2(v.y, v.x), h1 = bf2(v.w, v.z);
            float hx = __uint_as_float(h0 << 16), hy = __uint_as_float(h0 & 0xffff0000u);
            float hz = __uint_as_float(h1 << 16), hw = __uint_as_float(h1 & 0xffff0000u);
            uint32_t l0 = bf2(v.y - hy, v.x - hx), l1 = bf2(v.w - hw, v.z - hz);
            *reinterpret_cast<uint2*>(&Bh[r * LW + f * 2]) = make_uint2(h0, h1);
            *reinterpret_cast<uint2*>(&Bl[r * LW + f * 2]) = make_uint2(l0, l1);
        }
        if (c + 1 < NCHUNK) {
#pragma unroll
            for (int j = 0; j < APT; ++j) {
                int i = tid + j * 256;
                pa[j] = *reinterpret_cast<const float4*>(
                    A + (size_t)(brow + (i >> 3)) * KTOT + (c + 1) * 32 + ((i & 7) << 2));
            }
#pragma unroll
            for (int j = 0; j < BPT; ++j) {
                int i = tid + j * 256;
                pb[j] = *reinterpret_cast<const float4*>(
                    Bt + (size_t)(bcol + (i >> 3)) * KTOT + (c + 1) * 32 + ((i & 7) << 2));
            }
        }
        __syncthreads();

#pragma unroll
        for (int ks = 0; ks < 2; ++ks) {
            const int kw = ks * 8;
            uint32_t aH[MSUB][4], aL[MSUB][4];
#pragma unroll
            for (int ms = 0; ms < MSUB; ++ms) {
                int r0 = (warpM + ms * 16 + grp) * LW + kw + qk;
                int r1 = r0 + 8 * LW;
                aH[ms][0] = Ah[r0];     aH[ms][1] = Ah[r1];
                aH[ms][2] = Ah[r0 + 4]; aH[ms][3] = Ah[r1 + 4];
                aL[ms][0] = Al[r0];     aL[ms][1] = Al[r1];
                aL[ms][2] = Al[r0 + 4]; aL[ms][3] = Al[r1 + 4];
            }
            uint32_t bH[NSUB][2], bL[NSUB][2];
#pragma unroll
            for (int ns = 0; ns < NSUB; ++ns) {
                int b0 = (warpN + ns * 8 + grp) * LW + kw + qk;
                bH[ns][0] = Bh[b0]; bH[ns][1] = Bh[b0 + 4];
                bL[ns][0] = Bl[b0]; bL[ns][1] = Bl[b0 + 4];
            }
#pragma unroll
            for (int ms = 0; ms < MSUB; ++ms)
#pragma unroll
                for (int ns = 0; ns < NSUB; ++ns) {
                    mma_bf16(acc[ms][ns], aH[ms], bH[ns]);
                    mma_bf16(acc[ms][ns], aH[ms], bL[ns]);
                    mma_bf16(acc[ms][ns], aL[ms], bH[ns]);
                }
        }
        __syncthreads();
    }

#pragma unroll
    for (int ms = 0; ms < MSUB; ++ms)
#pragma unroll
        for (int ns = 0; ns < NSUB; ++ns) {
            int row = brow + warpM + ms * 16 + grp;
            int col = bcol + warpN + ns * 8 + 2 * qk;
            float2 v0 = make_float2(acc[ms][ns][0], acc[ms][ns][1]);
            float2 v1 = make_float2(acc[ms][ns][2], acc[ms][ns][3]);
            if (RELU) {
                v0.x = fmaxf(v0.x, 0.f); v0.y = fmaxf(v0.y, 0.f);
                v1.x = fmaxf(v1.x, 0.f); v1.y = fmaxf(v1.y, 0.f);
            }
            *reinterpret_cast<float2*>(C + (size_t)row * ldc + col)       = v0;
            *reinterpret_cast<float2*>(C + (size_t)(row + 8) * ldc + col) = v1;
        }
#if __CUDA_ARCH__ >= 900
    cudaTriggerProgrammaticLaunchCompletion();
#endif
}

// ---------------------------------------------------------------------------
// K4: agg2 + log_softmax. One warp per node; lanes = (neighbor-of-pair,
// col-quad). Branchless masked gather. PDL sync before dependent loads.
// ---------------------------------------------------------------------------
__global__ __launch_bounds__(256)
void agg_lsm_kernel(const float* __restrict__ T, const int* __restrict__ edge,
                    const unsigned* __restrict__ keep_in, float* __restrict__ out)
{
    const int node = (blockIdx.x * blockDim.x + threadIdx.x) >> 5;
    const int lane = threadIdx.x & 31;
    const int nbh  = lane >> 4;
    const int cq   = lane & 15;
    const int base = (node >> 8) << 8;

    int e = edge[node * DEG + cq];            // harness input — safe pre-sync

#if __CUDA_ARCH__ >= 900
    cudaGridDependencySynchronize();          // wait for gT (and keep) writes
#endif

    unsigned mask = keep_in[node];

    float4 a = make_float4(0.f, 0.f, 0.f, 0.f);
#pragma unroll
    for (int t = 0; t < 8; ++t) {
        int nb = 2 * t + nbh;
        int j  = __shfl_sync(0xffffffffu, e, nb);
        unsigned bit = (mask >> nb) & 1u;
        int jj = bit ? j : 0;
        float fm = (float)bit;
        float4 v = *reinterpret_cast<const float4*>(
            T + (size_t)(base + jj) * NCLASS + (cq << 2));
        a.x = fmaf(v.x, fm, a.x);
        a.y = fmaf(v.y, fm, a.y);
        a.z = fmaf(v.z, fm, a.z);
        a.w = fmaf(v.w, fm, a.w);
    }
    a.x += __shfl_xor_sync(0xffffffffu, a.x, 16);
    a.y += __shfl_xor_sync(0xffffffffu, a.y, 16);
    a.z += __shfl_xor_sync(0xffffffffu, a.z, 16);
    a.w += __shfl_xor_sync(0xffffffffu, a.w, 16);

    float mx = fmaxf(fmaxf(a.x, a.y), fmaxf(a.z, a.w));
#pragma unroll
    for (int o = 8; o; o >>= 1)
        mx = fmaxf(mx, __shfl_xor_sync(0xffffffffu, mx, o));
    float s = expf(a.x - mx) + expf(a.y - mx) + expf(a.z - mx) + expf(a.w - mx);
#pragma unroll
    for (int o = 8; o; o >>= 1)
        s += __shfl_xor_sync(0xffffffffu, s, o);
    float lse = logf(s) + mx;

    if (lane < 16)
        *reinterpret_cast<float4*>(out + (size_t)node * NCLASS + (cq << 2)) =
            make_float4(a.x - lse, a.y - lse, a.z - lse, a.w - lse);
}

// ---------------------------------------------------------------------------
extern "C" void kernel_launch(void* const* d_in, const int* in_sizes, int n_in,
                              void* d_out, int out_size)
{
    const float* x    = (const float*)d_in[0];
    const int*   edge = (const int*)  d_in[1];
    const float* W1   = (const float*)d_in[2];
    const float* W2   = (const float*)d_in[3];
    float* out = (float*)d_out;

    float *gX, *gH, *gT, *gW1t, *gW2t;
    unsigned *gK;
    cudaGetSymbolAddress((void**)&gX,   g_X);
    cudaGetSymbolAddress((void**)&gH,   g_H);
    cudaGetSymbolAddress((void**)&gT,   g_T);
    cudaGetSymbolAddress((void**)&gK,   g_keep);
    cudaGetSymbolAddress((void**)&gW1t, g_W1t);
    cudaGetSymbolAddress((void**)&gW2t, g_W2t);

    constexpr int SMEM1 = 2 * (2 * 128 + 2 * 128) * 20 * 4;   // 81920
    constexpr int SMEM2 = 2 * (2 * 64 + 2 * 64) * 20 * 4;     // 40960
    cudaFuncSetAttribute(agg1_kernel,
                         cudaFuncAttributeMaxDynamicSharedMemorySize, A1_SMEM_B);
    cudaFuncSetAttribute(gemm_bf16<128, 128, 128, 64, 32, true>,
                         cudaFuncAttributeMaxDynamicSharedMemorySize, SMEM1);
    cudaFuncSetAttribute(gemm_bf16<64, 64, 256, 32, 16, false>,
                         cudaFuncAttributeMaxDynamicSharedMemorySize, SMEM2);

    // K1: gX = adj @ x (smem-staged) + keep masks + W transposes
    agg1_kernel<<<176, 256, A1_SMEM_B>>>(x, edge, W1, W2, gX, gK, gW1t, gW2t);

    // PDL launch config for dependent kernels
    cudaLaunchAttribute pdlAttr;
    pdlAttr.id = cudaLaunchAttributeProgrammaticStreamSerialization;
    pdlAttr.val.programmaticStreamSerializationAllowed = 1;

    // K2: gH = relu(gX @ W1)
    {
        cudaLaunchConfig_t cfg = {};
        cfg.gridDim = dim3(64, 2, 1);
        cfg.blockDim = dim3(256, 1, 1);
        cfg.dynamicSmemBytes = SMEM1;
        cfg.attrs = &pdlAttr;
        cfg.numAttrs = 1;
        cudaLaunchKernelEx(&cfg, gemm_bf16<128, 128, 128, 64, 32, true>,
                           (const float*)gX, (const float*)gW1t, gH, (int)NHID);
    }
    // K3: gT = gH @ W2
    {
        cudaLaunchConfig_t cfg = {};
        cfg.gridDim = dim3(128, 1, 1);
        cfg.blockDim = dim3(256, 1, 1);
        cfg.dynamicSmemBytes = SMEM2;
        cfg.attrs = &pdlAttr;
        cfg.numAttrs = 1;
        cudaLaunchKernelEx(&cfg, gemm_bf16<64, 64, 256, 32, 16, false>,
                           (const float*)gH, (const float*)gW2t, gT, (int)NCLASS);
    }
    // K4: out = log_softmax(adj @ gT)
    {
        cudaLaunchConfig_t cfg = {};
        cfg.gridDim = dim3(NN / 8, 1, 1);
        cfg.blockDim = dim3(256, 1, 1);
        cfg.dynamicSmemBytes = 0;
        cfg.attrs = &pdlAttr;
        cfg.numAttrs = 1;
        cudaLaunchKernelEx(&cfg, agg_lsm_kernel,
                           (const float*)gT, edge, (const unsigned*)gK, out);
    }
}

// round 16
// speedup vs baseline: 1.3856x; 1.3774x over previous
#include <cuda_runtime.h>
#include <cuda_bf16.h>
#include <cstdint>

#define NN      8192
#define NODE    256
#define DEG     16
#define NFEAT   128
#define NHID    256
#define NCLASS  64

// ---------------- device scratch (no allocation allowed) --------------------
__device__ float    g_X  [NN * NFEAT];    // adj @ x
__device__ float    g_H  [NN * NHID];     // relu(gX @ W1)
__device__ float    g_T  [NN * NCLASS];   // gH @ W2
__device__ unsigned g_keep[NN];           // dedup bitmask per node
__device__ float    g_W1t[NHID * NFEAT];  // W1^T
__device__ float    g_W2t[NCLASS * NHID]; // W2^T

// pack two f32 -> bf16x2 (hi arg = upper half)
__device__ __forceinline__ uint32_t bf2(float hi, float lo) {
    uint32_t r; asm("cvt.rn.bf16x2.f32 %0, %1, %2;" : "=r"(r) : "f"(hi), "f"(lo));
    return r;
}
__device__ __forceinline__ void mma_bf16(float c[4], const uint32_t a[4], const uint32_t b[2]) {
    asm volatile(
        "mma.sync.aligned.m16n8k16.row.col.f32.bf16.bf16.f32 "
        "{%0,%1,%2,%3}, {%4,%5,%6,%7}, {%8,%9}, {%0,%1,%2,%3};"
        : "+f"(c[0]), "+f"(c[1]), "+f"(c[2]), "+f"(c[3])
        : "r"(a[0]), "r"(a[1]), "r"(a[2]), "r"(a[3]), "r"(b[0]), "r"(b[1]));
}
__device__ __forceinline__ void ldsm_x4(uint32_t r[4], uint32_t addr) {
    asm volatile("ldmatrix.sync.aligned.m8n8.x4.shared.b16 {%0,%1,%2,%3}, [%4];"
        : "=r"(r[0]), "=r"(r[1]), "=r"(r[2]), "=r"(r[3]) : "r"(addr));
}
__device__ __forceinline__ void ldsm_x2(uint32_t r[2], uint32_t addr) {
    asm volatile("ldmatrix.sync.aligned.m8n8.x2.shared.b16 {%0,%1}, [%2];"
        : "=r"(r[0]), "=r"(r[1]) : "r"(addr));
}

// Dynamic smem sizes for agg1
#define A1_SMX_FLT   (NODE * 32)
#define A1_EDGE_INT  (NODE * DEG)
#define A1_SMEM_B    ((A1_SMX_FLT + A1_EDGE_INT + NODE + NODE) * 4)

// ---------------------------------------------------------------------------
// K1: blocks 0..127 : agg1 — smem-staged adj @ x. CTA = (block, 32-col slice).
//     Also writes dedup masks (g==0 CTAs). blocks 128..175: W transposes.
// ---------------------------------------------------------------------------
__global__ __launch_bounds__(256)
void agg1_kernel(const float* __restrict__ x, const int* __restrict__ edge,
                 const float* __restrict__ W1, const float* __restrict__ W2,
                 float* __restrict__ gX, unsigned* __restrict__ keep_out,
                 float* __restrict__ W1t, float* __restrict__ W2t)
{
    extern __shared__ float dyn[];
    const int bid = blockIdx.x;
    const int tid = threadIdx.x;

    if (bid < 128) {
        float*    smx   = dyn;                                           // [256][32]
        int*      sedge = reinterpret_cast<int*>(dyn + A1_SMX_FLT);      // [256][16]
        unsigned* smask = reinterpret_cast<unsigned*>(sedge + A1_EDGE_INT);

        const int blk  = bid >> 2;
        const int g    = bid & 3;
        const int base = blk * NODE;

#pragma unroll
        for (int i = tid; i < NODE * 8; i += 256) {
            int r = i >> 3, qd = i & 7;
            *reinterpret_cast<float4*>(&smx[r * 32 + qd * 4]) =
                *reinterpret_cast<const float4*>(
                    x + (size_t)(base + r) * NFEAT + g * 32 + qd * 4);
        }
        {
            const int4* ep = reinterpret_cast<const int4*>(edge + (size_t)(base + tid) * DEG);
            int4 v0 = ep[0], v1 = ep[1], v2 = ep[2], v3 = ep[3];
            int e[16] = {v0.x, v0.y, v0.z, v0.w, v1.x, v1.y, v1.z, v1.w,
                         v2.x, v2.y, v2.z, v2.w, v3.x, v3.y, v3.z, v3.w};
            unsigned mask = 0;
#pragma unroll
            for (int i = 0; i < 16; ++i) {
                bool keep = e[i] >= 0;
#pragma unroll
                for (int p = 0; p < i; ++p) keep = keep && (e[i] != e[p]);
                if (keep) mask |= 1u << i;
                sedge[tid * DEG + i] = (e[i] >= 0) ? e[i] : 0;
            }
            smask[tid] = mask;
            if (g == 0) keep_out[base + tid] = mask;
        }
        __syncthreads();

#pragma unroll
        for (int p = 0; p < 8; ++p) {
            const int nl = p * 32 + (tid >> 3);
            const int qd = tid & 7;
            const unsigned mask = smask[nl];
            float4 a = make_float4(0.f, 0.f, 0.f, 0.f);
#pragma unroll
            for (int t = 0; t < DEG; ++t) {
                int   j  = sedge[nl * DEG + t];
                float fm = (float)((mask >> t) & 1u);
                float4 v = *reinterpret_cast<const float4*>(&smx[j * 32 + qd * 4]);
                a.x = fmaf(v.x, fm, a.x);
                a.y = fmaf(v.y, fm, a.y);
                a.z = fmaf(v.z, fm, a.z);
                a.w = fmaf(v.w, fm, a.w);
            }
            *reinterpret_cast<float4*>(
                gX + (size_t)(base + nl) * NFEAT + g * 32 + qd * 4) = a;
        }
    } else {
        float* t = dyn;                         // [32][33]
        const float* src; float* dst; int R, C, tr, tc;
        if (bid < 160) { int b = bid - 128; src = W1; dst = W1t; R = NFEAT; C = NHID;  tr = b >> 3; tc = b & 7; }
        else           { int b = bid - 160; src = W2; dst = W2t; R = NHID;  C = NCLASS; tr = b >> 1; tc = b & 1; }
        const int r  = tid >> 3;
        const int fq = tid & 7;
        float4 v = *reinterpret_cast<const float4*>(src + (size_t)(tr * 32 + r) * C + tc * 32 + fq * 4);
        t[r * 33 + fq * 4 + 0] = v.x; t[r * 33 + fq * 4 + 1] = v.y;
        t[r * 33 + fq * 4 + 2] = v.z; t[r * 33 + fq * 4 + 3] = v.w;
        __syncthreads();
        float4 o;
        o.x = t[(fq * 4 + 0) * 33 + r]; o.y = t[(fq * 4 + 1) * 33 + r];
        o.z = t[(fq * 4 + 2) * 33 + r]; o.w = t[(fq * 4 + 3) * 33 + r];
        *reinterpret_cast<float4*>(dst + (size_t)(tc * 32 + r) * R + tr * 32 + fq * 4) = o;
    }
}

// ---------------------------------------------------------------------------
// bf16 mma.sync GEMM (m16n8k16), 3xBF16 compensation, double-buffered,
// ldmatrix fragment loading.
// ---------------------------------------------------------------------------
template<int BM, int BN, int KTOT, int WM, int WN, bool RELU>
__global__ __launch_bounds__(256)
void gemm_bf16(const float* __restrict__ A, const float* __restrict__ Bt,
               float* __restrict__ C, int ldc)
{
    constexpr int LW     = 20;                // words per 32-k row (16 + 4 pad)
    constexpr int NWN    = BN / WN;
    constexpr int MSUB   = WM / 16;
    constexpr int NSUB   = WN / 8;
    constexpr int NCHUNK = KTOT / 32;
    constexpr int A_W    = BM * LW;
    constexpr int B_W    = BN * LW;
    constexpr int STAGE_W = 2 * A_W + 2 * B_W;
    constexpr int APT    = BM * 8 / 256;
    constexpr int BPT    = BN * 8 / 256;

    extern __shared__ uint32_t smw[];

    const int tid   = threadIdx.x;
    const int wid   = tid >> 5;
    const int lane  = tid & 31;
    const int brow  = blockIdx.x * BM;
    const int bcol  = blockIdx.y * BN;
    const int warpM = (wid / NWN) * WM;
    const int warpN = (wid % NWN) * WN;
    const int grp   = lane >> 2;
    const int qk    = lane & 3;

    // ldmatrix per-lane address components
    const int laneArow = warpM + (lane & 7) + (lane & 8);  // M0/M1/M2/M3 rows
    const int laneAcol = (lane >> 4) << 2;                 // 0 or 4 (k-half)
    const int laneBrow = warpN + (lane & 7);
    const int laneBcol = ((lane >> 3) & 1) << 2;

    float acc[MSUB][NSUB][4] = {};
    float4 pa[APT], pb[BPT];

#pragma unroll
    for (int j = 0; j < APT; ++j) {
        int i = tid + j * 256;
        pa[j] = *reinterpret_cast<const float4*>(
            A + (size_t)(brow + (i >> 3)) * KTOT + ((i & 7) << 2));
    }
#pragma unroll
    for (int j = 0; j < BPT; ++j) {
        int i = tid + j * 256;
        pb[j] = *reinterpret_cast<const float4*>(
            Bt + (size_t)(bcol + (i >> 3)) * KTOT + ((i & 7) << 2));
    }

    for (int c = 0; c < NCHUNK; ++c) {
        uint32_t* Ah = smw + (c & 1) * STAGE_W;
        uint32_t* Al = Ah + A_W;
        uint32_t* Bh = Al + A_W;
        uint32_t* Bl = Bh + B_W;

#pragma unroll
        for (int j = 0; j < APT; ++j) {
            int i = tid + j * 256;
            int r = i >> 3, f = i & 7;
            float4 v = pa[j];
            uint32_t h0 = bf2(v.y, v.x), h1 = bf2(v.w, v.z);
            float hx = __uint_as_float(h0 << 16), hy = __uint_as_float(h0 & 0xffff0000u);
            float hz = __uint_as_float(h1 << 16), hw = __uint_as_float(h1 & 0xffff0000u);
            uint32_t l0 = bf2(v.y - hy, v.x - hx), l1 = bf2(v.w - hw, v.z - hz);
            *reinterpret_cast<uint2*>(&Ah[r * LW + f * 2]) = make_uint2(h0, h1);
            *reinterpret_cast<uint2*>(&Al[r * LW + f * 2]) = make_uint2(l0, l1);
        }
#pragma unroll
        for (int j = 0; j < BPT; ++j) {
            int i = tid + j * 256;
            int r = i >> 3, f = i & 7;
            float4 v = pb[j];
            uint32_t h0 = bf2(v.y, v.x), h1 = bf2(v.w, v.z);
            float hx = __uint_as_float(h0 << 16), hy = __uint_as_float(h0 & 0xffff0000u);
            float hz = __uint_as_float(h1 << 16), hw = __uint_as_float(h1 & 0xffff0000u);
            uint32_t l0 = bf2(v.y - hy, v.x - hx), l1 = bf2(v.w - hw, v.z - hz);
            *reinterpret_cast<uint2*>(&Bh[r * LW + f * 2]) = make_uint2(h0, h1);
            *reinterpret_cast<uint2*>(&Bl[r * LW + f * 2]) = make_uint2(l0, l1);
        }
        if (c + 1 < NCHUNK) {
#pragma unroll
            for (int j = 0; j < APT; ++j) {
                int i = tid + j * 256;
                pa[j] = *reinterpret_cast<const float4*>(
                    A + (size_t)(brow + (i >> 3)) * KTOT + (c + 1) * 32 + ((i & 7) << 2));
            }
#pragma unroll
            for (int j = 0; j < BPT; ++j) {
                int i = tid + j * 256;
                pb[j] = *reinterpret_cast<const float4*>(
                    Bt + (size_t)(bcol + (i >> 3)) * KTOT + (c + 1) * 32 + ((i & 7) << 2));
            }
        }
        __syncthreads();

        const uint32_t aSh = (uint32_t)__cvta_generic_to_shared(Ah)
                           + (uint32_t)((laneArow * LW + laneAcol) * 4);
        const uint32_t bSh = (uint32_t)__cvta_generic_to_shared(Bh)
                           + (uint32_t)((laneBrow * LW + laneBcol) * 4);

#pragma unroll
        for (int ks = 0; ks < 2; ++ks) {
            const int kw = ks * 8;
            uint32_t aH[MSUB][4], aL[MSUB][4];
#pragma unroll
            for (int ms = 0; ms < MSUB; ++ms) {
                uint32_t ad = aSh + (uint32_t)((ms * 16 * LW + kw) * 4);
                ldsm_x4(aH[ms], ad);
                ldsm_x4(aL[ms], ad + A_W * 4);
            }
            uint32_t bH[NSUB][2], bL[NSUB][2];
#pragma unroll
            for (int ns = 0; ns < NSUB; ++ns) {
                uint32_t bd = bSh + (uint32_t)((ns * 8 * LW + kw) * 4);
                ldsm_x2(bH[ns], bd);
                ldsm_x2(bL[ns], bd + B_W * 4);
            }
#pragma unroll
            for (int ms = 0; ms < MSUB; ++ms)
#pragma unroll
                for (int ns = 0; ns < NSUB; ++ns) {
                    mma_bf16(acc[ms][ns], aH[ms], bH[ns]);
                    mma_bf16(acc[ms][ns], aH[ms], bL[ns]);
                    mma_bf16(acc[ms][ns], aL[ms], bH[ns]);
                }
        }
        __syncthreads();
    }

#pragma unroll
    for (int ms = 0; ms < MSUB; ++ms)
#pragma unroll
        for (int ns = 0; ns < NSUB; ++ns) {
            int row = brow + warpM + ms * 16 + grp;
            int col = bcol + warpN + ns * 8 + 2 * qk;
            float2 v0 = make_float2(acc[ms][ns][0], acc[ms][ns][1]);
            float2 v1 = make_float2(acc[ms][ns][2], acc[ms][ns][3]);
            if (RELU) {
                v0.x = fmaxf(v0.x, 0.f); v0.y = fmaxf(v0.y, 0.f);
                v1.x = fmaxf(v1.x, 0.f); v1.y = fmaxf(v1.y, 0.f);
            }
            *reinterpret_cast<float2*>(C + (size_t)row * ldc + col)       = v0;
            *reinterpret_cast<float2*>(C + (size_t)(row + 8) * ldc + col) = v1;
        }
}

// ---------------------------------------------------------------------------
// K4: agg2 + log_softmax. One warp per node; lanes = (neighbor-of-pair,
// col-quad). Branchless masked gather (R12-proven).
// ---------------------------------------------------------------------------
__global__ __launch_bounds__(256)
void agg_lsm_kernel(const float* __restrict__ T, const int* __restrict__ edge,
                    const unsigned* __restrict__ keep_in, float* __restrict__ out)
{
    const int node = (blockIdx.x * blockDim.x + threadIdx.x) >> 5;
    const int lane = threadIdx.x & 31;
    const int nbh  = lane >> 4;
    const int cq   = lane & 15;
    const int base = (node >> 8) << 8;

    int e = edge[node * DEG + cq];
    unsigned mask = keep_in[node];

    float4 a = make_float4(0.f, 0.f, 0.f, 0.f);
#pragma unroll
    for (int t = 0; t < 8; ++t) {
        int nb = 2 * t + nbh;
        int j  = __shfl_sync(0xffffffffu, e, nb);
        unsigned bit = (mask >> nb) & 1u;
        int jj = bit ? j : 0;
        float fm = (float)bit;
        float4 v = *reinterpret_cast<const float4*>(
            T + (size_t)(base + jj) * NCLASS + (cq << 2));
        a.x = fmaf(v.x, fm, a.x);
        a.y = fmaf(v.y, fm, a.y);
        a.z = fmaf(v.z, fm, a.z);
        a.w = fmaf(v.w, fm, a.w);
    }
    a.x += __shfl_xor_sync(0xffffffffu, a.x, 16);
    a.y += __shfl_xor_sync(0xffffffffu, a.y, 16);
    a.z += __shfl_xor_sync(0xffffffffu, a.z, 16);
    a.w += __shfl_xor_sync(0xffffffffu, a.w, 16);

    float mx = fmaxf(fmaxf(a.x, a.y), fmaxf(a.z, a.w));
#pragma unroll
    for (int o = 8; o; o >>= 1)
        mx = fmaxf(mx, __shfl_xor_sync(0xffffffffu, mx, o));
    float s = expf(a.x - mx) + expf(a.y - mx) + expf(a.z - mx) + expf(a.w - mx);
#pragma unroll
    for (int o = 8; o; o >>= 1)
        s += __shfl_xor_sync(0xffffffffu, s, o);
    float lse = logf(s) + mx;

    if (lane < 16)
        *reinterpret_cast<float4*>(out + (size_t)node * NCLASS + (cq << 2)) =
            make_float4(a.x - lse, a.y - lse, a.z - lse, a.w - lse);
}

// ---------------------------------------------------------------------------
extern "C" void kernel_launch(void* const* d_in, const int* in_sizes, int n_in,
                              void* d_out, int out_size)
{
    const float* x    = (const float*)d_in[0];
    const int*   edge = (const int*)  d_in[1];
    const float* W1   = (const float*)d_in[2];
    const float* W2   = (const float*)d_in[3];
    float* out = (float*)d_out;

    float *gX, *gH, *gT, *gW1t, *gW2t;
    unsigned *gK;
    cudaGetSymbolAddress((void**)&gX,   g_X);
    cudaGetSymbolAddress((void**)&gH,   g_H);
    cudaGetSymbolAddress((void**)&gT,   g_T);
    cudaGetSymbolAddress((void**)&gK,   g_keep);
    cudaGetSymbolAddress((void**)&gW1t, g_W1t);
    cudaGetSymbolAddress((void**)&gW2t, g_W2t);

    constexpr int SMEM1 = 2 * (2 * 128 + 2 * 128) * 20 * 4;   // 81920
    constexpr int SMEM2 = 2 * (2 * 64 + 2 * 64) * 20 * 4;     // 40960
    cudaFuncSetAttribute(agg1_kernel,
                         cudaFuncAttributeMaxDynamicSharedMemorySize, A1_SMEM_B);
    cudaFuncSetAttribute(gemm_bf16<128, 128, 128, 64, 32, true>,
                         cudaFuncAttributeMaxDynamicSharedMemorySize, SMEM1);
    cudaFuncSetAttribute(gemm_bf16<64, 64, 256, 32, 16, false>,
                         cudaFuncAttributeMaxDynamicSharedMemorySize, SMEM2);

    // K1: gX = adj @ x (smem-staged, branchless) + keep masks + W transposes
    agg1_kernel<<<176, 256, A1_SMEM_B>>>(x, edge, W1, W2, gX, gK, gW1t, gW2t);
    // K2: gH = relu(gX @ W1)
    gemm_bf16<128, 128, 128, 64, 32, true>
        <<<dim3(64, 2), 256, SMEM1>>>(gX, gW1t, gH, NHID);
    // K3: gT = gH @ W2
    gemm_bf16<64, 64, 256, 32, 16, false>
        <<<dim3(128, 1), 256, SMEM2>>>(gH, gW2t, gT, NCLASS);
    // K4: out = log_softmax(adj @ gT)  (branchless gather)
    agg_lsm_kernel<<<NN / 8, 256>>>(gT, edge, gK, out);
}